// round 7
// baseline (speedup 1.0000x reference)
#include <cuda_runtime.h>
#include <cuda_bf16.h>
#include <cstdint>

// ---------------- problem constants ----------------
#define N_ROWS   262144
#define DIMS     64
#define KCODES   1024
#define BM       128
#define THREADS  512
#define GRID     (N_ROWS / BM)              // 2048
#define QOUT     (N_ROWS * DIMS)
#define CAND_CAP 8
#define NCHUNK   8                          // 8 chunks of 128 codes
#define CHUNK_B  18432                      // 128 codes x 144B

// ---------------- smem layout (bytes) ----------------
#define SM_A     0                          // 128 rows x 144B bf16
#define SM_B     18432                      // 3 x 18432 streamed B buffers
#define SM_CN    73728                      // 1024 fp32
#define SM_GM    77824                      // [warp][chunk][row16] fp32 = 8192
#define SM_CA    86016                      // 128 x 8 x 8B candidates
#define SM_RM    94208                      // 128 u32 keys (reused in finalize)
#define SM_CT    94720                      // 128 int
#define SM_TK    95232                      // 128 int
#define SM_DL    95744                      // 128 fp32
#define SM_XN    96256                      // 128 fp32 row |x|^2
#define SM_NEED  96768                      // 8 int
#define SM_LST   96800                      // 8 int + count
#define SM_FLAG  96840                      // 4B
#define SMEM_TOTAL 96896

#define A_STRIDE 144
#define B_STRIDE 144

// ---------------- device globals ----------------
__device__ __align__(16) float    g_cnorm[KCODES];
__device__ __align__(16) uint32_t g_cbbf16[KCODES * DIMS / 2];
__device__ unsigned int           g_counts[KCODES];
__device__ float                  g_loss[2];
__device__ int                    g_cmax_bits;
__device__ unsigned int           g_done;

// ---------------- helpers ----------------
static __device__ __forceinline__ unsigned fkey(float f) {
    int b = __float_as_int(f);
    return (unsigned)(b >= 0 ? (b | 0x80000000) : ~b);
}
static __device__ __forceinline__ float finv(unsigned k) {
    int b = (k & 0x80000000u) ? (int)(k & 0x7fffffffu) : ~(int)k;
    return __int_as_float(b);
}
static __device__ __forceinline__ uint32_t smem_u32(const void* p) {
    uint32_t a;
    asm("{ .reg .u64 t; cvta.to.shared.u64 t, %1; cvt.u32.u64 %0, t; }" : "=r"(a) : "l"(p));
    return a;
}
static __device__ __forceinline__ void mma16816(
    float& c0, float& c1, float& c2, float& c3,
    uint32_t a0, uint32_t a1, uint32_t a2, uint32_t a3,
    uint32_t b0, uint32_t b1)
{
    asm volatile(
        "mma.sync.aligned.m16n8k16.row.col.f32.bf16.bf16.f32 "
        "{%0,%1,%2,%3}, {%4,%5,%6,%7}, {%8,%9}, {%0,%1,%2,%3};"
        : "+f"(c0), "+f"(c1), "+f"(c2), "+f"(c3)
        : "r"(a0), "r"(a1), "r"(a2), "r"(a3), "r"(b0), "r"(b1));
}
static __device__ __forceinline__ void cp16(uint32_t dst, const uint32_t* gsrc) {
    asm volatile(
        "{ .reg .u64 g; cvta.to.global.u64 g, %1; cp.async.cg.shared.global [%0], [g], 16; }"
        :: "r"(dst), "l"(gsrc));
}
#define CP_COMMIT() asm volatile("cp.async.commit_group;" ::: "memory")
static __device__ __forceinline__ void cp_wait(int n) {
    if (n <= 0)      asm volatile("cp.async.wait_group 0;" ::: "memory");
    else if (n == 1) asm volatile("cp.async.wait_group 1;" ::: "memory");
    else             asm volatile("cp.async.wait_group 2;" ::: "memory");
}
// stream one 128-code chunk of bf16 codebook into buffer `buf`
static __device__ __forceinline__ void issue_chunk(uint32_t sb_B, int chunk, int buf, int tid) {
#pragma unroll
    for (int q = 0; q < 2; q++) {
        int e = tid + q * THREADS;          // 0..1023
        int code = e >> 3, j = e & 7;
        const uint32_t* src = g_cbbf16 + ((size_t)chunk * 128 + code) * 32 + j * 4;
        uint32_t dst = sb_B + buf * CHUNK_B + code * B_STRIDE + j * 16;
        cp16(dst, src);
    }
    CP_COMMIT();
}

// ---------------- prep: resets + cnorm + cmax + bf16 codebook ----------------
__global__ void vq_prep(const float* __restrict__ cb) {
    int k = threadIdx.x;   // 1024 threads, 1 block
    g_counts[k] = 0u;
    if (k < 2) g_loss[k] = 0.0f;
    if (k == 2) g_done = 0u;

    const float4* c4 = (const float4*)(cb + (size_t)k * DIMS);
    uint32_t* ob = g_cbbf16 + k * (DIMS / 2);
    float s = 0.0f;
#pragma unroll
    for (int j = 0; j < 16; j++) {
        float4 v = c4[j];
        s += v.x * v.x + v.y * v.y + v.z * v.z + v.w * v.w;
        __nv_bfloat162 p0 = __float22bfloat162_rn(make_float2(v.x, v.y));
        __nv_bfloat162 p1 = __float22bfloat162_rn(make_float2(v.z, v.w));
        ob[j * 2 + 0] = *(uint32_t*)&p0;
        ob[j * 2 + 1] = *(uint32_t*)&p1;
    }
    g_cnorm[k] = 0.5f * s;
    atomicMax(&g_cmax_bits, __float_as_int(sqrtf(s)));
}

// ---------------- main ----------------
extern __shared__ char smem[];

__global__ __launch_bounds__(THREADS, 2)
void vq_main(const float* __restrict__ inp, const float* __restrict__ cb,
             float* __restrict__ out)
{
    const int tid  = threadIdx.x;
    const int w    = tid >> 5;
    const int lane = tid & 31;
    const int row0 = blockIdx.x * BM;
    const uint32_t sbase = smem_u32(smem);

    char*     As = smem + SM_A;
    float*    CN = (float*)(smem + SM_CN);
    float*    GM = (float*)(smem + SM_GM);
    float2*   CA = (float2*)(smem + SM_CA);
    unsigned* RM = (unsigned*)(smem + SM_RM);
    int*      CT = (int*)(smem + SM_CT);
    int*      TK = (int*)(smem + SM_TK);
    float*    DL = (float*)(smem + SM_DL);
    float*    XN = (float*)(smem + SM_XN);
    int*      NEED = (int*)(smem + SM_NEED);
    int*      LST  = (int*)(smem + SM_LST);
    int*      FLAG = (int*)(smem + SM_FLAG);

    // ---- start streaming B chunks 0..2 immediately ----
    issue_chunk(sbase + SM_B, 0, 0, tid);
    issue_chunk(sbase + SM_B, 1, 1, tid);
    issue_chunk(sbase + SM_B, 2, 2, tid);

    // ---- fills: A bf16 + row norms + cnorm + inits ----
    if (tid < 128) { RM[tid] = 0u; CT[tid] = 0; }
    if (tid < 8)   NEED[tid] = 0;
#pragma unroll
    for (int i = 0; i < 4; i++) {
        int idx = tid + i * THREADS;        // 2048 = 128 rows x 16 f4
        int r = idx >> 4, j = idx & 15;
        float4 v = *(const float4*)(inp + (size_t)(row0 + r) * DIMS + j * 4);
        __nv_bfloat162 p0 = __float22bfloat162_rn(make_float2(v.x, v.y));
        __nv_bfloat162 p1 = __float22bfloat162_rn(make_float2(v.z, v.w));
        *(uint2*)(As + r * A_STRIDE + j * 8) = make_uint2(*(uint32_t*)&p0, *(uint32_t*)&p1);
        float s = v.x * v.x + v.y * v.y + v.z * v.z + v.w * v.w;
        // 16 consecutive lanes share a row: xor-reduce within 16-lane halves
        s += __shfl_xor_sync(0xffffffffu, s, 8);
        s += __shfl_xor_sync(0xffffffffu, s, 4);
        s += __shfl_xor_sync(0xffffffffu, s, 2);
        s += __shfl_xor_sync(0xffffffffu, s, 1);
        if ((lane & 15) == 0) XN[r] = s;
    }
#pragma unroll
    for (int i = 0; i < 2; i++) CN[tid + i * THREADS] = g_cnorm[tid + i * THREADS];
    __syncthreads();

    // ---- warp work assignment: 16 rows x 64 cols per chunk ----
    const int wrow  = (w & 7) * 16;
    const int choff = (w >> 3) * 64;
    const int r0 = wrow + (lane >> 2);
    const int r1 = r0 + 8;

    // ---- A fragments: persistent registers (4 ks x 4) ----
    uint32_t af[4][4];
#pragma unroll
    for (int ks = 0; ks < 4; ks++) {
        int kb = ks * 32 + (lane & 3) * 4;
        af[ks][0] = *(const uint32_t*)(As + r0 * A_STRIDE + kb);
        af[ks][1] = *(const uint32_t*)(As + r1 * A_STRIDE + kb);
        af[ks][2] = *(const uint32_t*)(As + r0 * A_STRIDE + kb + 16);
        af[ks][3] = *(const uint32_t*)(As + r1 * A_STRIDE + kb + 16);
    }

    // ================= PASS 1: streamed chunks, exact approx-max =================
    float rm0 = -3.4e38f, rm1 = -3.4e38f;
    for (int c = 0; c < NCHUNK; c++) {
        cp_wait(min(2, (NCHUNK - 1) - c));
        __syncthreads();
        const char* Bb = smem + SM_B + (c % 3) * CHUNK_B;
        float cm0 = -3.4e38f, cm1 = -3.4e38f;
#pragma unroll
        for (int j = 0; j < 8; j++) {
            int colL = choff + j * 8;
            int colG = c * 128 + colL;
            float2 cn = *(const float2*)(CN + colG + (lane & 3) * 2);
            float a0 = -cn.x, a1 = -cn.y, a2 = -cn.x, a3 = -cn.y;
            const char* bp = Bb + (colL + (lane >> 2)) * B_STRIDE + (lane & 3) * 4;
#pragma unroll
            for (int ks = 0; ks < 4; ks++) {
                uint32_t b0 = *(const uint32_t*)(bp + ks * 32);
                uint32_t b1 = *(const uint32_t*)(bp + ks * 32 + 16);
                mma16816(a0, a1, a2, a3, af[ks][0], af[ks][1], af[ks][2], af[ks][3], b0, b1);
            }
            cm0 = fmaxf(cm0, fmaxf(a0, a1));
            cm1 = fmaxf(cm1, fmaxf(a2, a3));
        }
        // quad-combine (4 lanes of a quad share rows r0,r1)
        cm0 = fmaxf(cm0, __shfl_xor_sync(0xffffffffu, cm0, 1));
        cm0 = fmaxf(cm0, __shfl_xor_sync(0xffffffffu, cm0, 2));
        cm1 = fmaxf(cm1, __shfl_xor_sync(0xffffffffu, cm1, 1));
        cm1 = fmaxf(cm1, __shfl_xor_sync(0xffffffffu, cm1, 2));
        rm0 = fmaxf(rm0, cm0);
        rm1 = fmaxf(rm1, cm1);
        if ((lane & 3) == 0) {
            GM[(w * NCHUNK + c) * 16 + (lane >> 2)]     = cm0;
            GM[(w * NCHUNK + c) * 16 + 8 + (lane >> 2)] = cm1;
        }
        __syncthreads();
        if (c + 3 < NCHUNK) issue_chunk(sbase + SM_B, c + 3, (c + 3) % 3, tid);
    }
    if ((lane & 3) == 0) {
        atomicMax(&RM[r0], fkey(rm0));
        atomicMax(&RM[r1], fkey(rm1));
    }
    // per-row certified margin delta (XN ready since first barrier)
    if (tid < 128)
        DL[tid] = sqrtf(XN[tid]) * __int_as_float(g_cmax_bits) * (2.2f / 256.0f) + 1e-4f;
    __syncthreads();

    // ---- chunk need mask ----
    if (tid < 128) {
        int ww = tid >> 3, c = tid & 7;
        int base = (ww & 7) * 16;
        int flag = 0;
#pragma unroll
        for (int r = 0; r < 16; r++) {
            float thr = finv(RM[base + r]) - DL[base + r];
            if (GM[(ww * NCHUNK + c) * 16 + r] >= thr) flag = 1;
        }
        if (flag) atomicOr(&NEED[c], 1);
    }
    __syncthreads();
    if (tid == 0) {
        int m = 0;
#pragma unroll
        for (int c = 0; c < NCHUNK; c++) if (NEED[c]) LST[m++] = c;
        LST[8] = m;
    }
    __syncthreads();

    // ================= PASS 2: re-stream needed chunks, collect candidates =====
    const int m = LST[8];
    const float thra = finv(RM[r0]) - DL[r0];
    const float thrb = finv(RM[r1]) - DL[r1];
    float trow = 3.4e38f;
    if (lane < 16) trow = finv(RM[wrow + lane]) - DL[wrow + lane];

    for (int p = 0; p < 3 && p < m; p++) issue_chunk(sbase + SM_B, LST[p], p, tid);
    for (int i = 0; i < m; i++) {
        cp_wait(min(2, (m - 1) - i));
        __syncthreads();
        int c = LST[i];
        bool mine = (lane < 16) && (GM[(w * NCHUNK + c) * 16 + lane] >= trow);
        if (__any_sync(0xffffffffu, mine)) {
            const char* Bb = smem + SM_B + (i % 3) * CHUNK_B;
#pragma unroll
            for (int j = 0; j < 8; j++) {
                int colL = choff + j * 8;
                int col0 = c * 128 + colL + (lane & 3) * 2;
                float2 cn = *(const float2*)(CN + col0);
                float a0 = -cn.x, a1 = -cn.y, a2 = -cn.x, a3 = -cn.y;
                const char* bp = Bb + (colL + (lane >> 2)) * B_STRIDE + (lane & 3) * 4;
#pragma unroll
                for (int ks = 0; ks < 4; ks++) {
                    uint32_t b0 = *(const uint32_t*)(bp + ks * 32);
                    uint32_t b1 = *(const uint32_t*)(bp + ks * 32 + 16);
                    mma16816(a0, a1, a2, a3, af[ks][0], af[ks][1], af[ks][2], af[ks][3], b0, b1);
                }
                if (a0 >= thra) {
                    int q = atomicAdd(&CT[r0], 1);
                    if (q < CAND_CAP) CA[r0 * CAND_CAP + q] = make_float2(a0, __int_as_float(col0));
                }
                if (a1 >= thra) {
                    int q = atomicAdd(&CT[r0], 1);
                    if (q < CAND_CAP) CA[r0 * CAND_CAP + q] = make_float2(a1, __int_as_float(col0 + 1));
                }
                if (a2 >= thrb) {
                    int q = atomicAdd(&CT[r1], 1);
                    if (q < CAND_CAP) CA[r1 * CAND_CAP + q] = make_float2(a2, __int_as_float(col0));
                }
                if (a3 >= thrb) {
                    int q = atomicAdd(&CT[r1], 1);
                    if (q < CAND_CAP) CA[r1 * CAND_CAP + q] = make_float2(a3, __int_as_float(col0 + 1));
                }
            }
        }
        __syncthreads();
        if (i + 3 < m) issue_chunk(sbase + SM_B, LST[i + 3], (i + 3) % 3, tid);
    }
    __syncthreads();

    // ---- exact fp32 rescore (1 thread per row, x from gmem) ----
    if (tid < 128) {
        int r = tid;
        int n = CT[r];
        const float4* xr = (const float4*)(inp + (size_t)(row0 + r) * DIMS);
        float bestS = -3.4e38f;
        int   bestI = KCODES;
        if (n <= CAND_CAP) {
            for (int i = 0; i < n; i++) {
                float2 ce = CA[r * CAND_CAP + i];
                int ix = __float_as_int(ce.y);
                const float4* c4 = (const float4*)(cb + (size_t)ix * DIMS);
                float a0 = 0.f, a1 = 0.f, a2 = 0.f, a3 = 0.f;
#pragma unroll
                for (int q = 0; q < 16; q++) {
                    float4 cv = c4[q];
                    float4 xv = xr[q];
                    a0 = fmaf(xv.x, cv.x, a0);
                    a1 = fmaf(xv.y, cv.y, a1);
                    a2 = fmaf(xv.z, cv.z, a2);
                    a3 = fmaf(xv.w, cv.w, a3);
                }
                float s = (a0 + a1) + (a2 + a3) - CN[ix];
                if (s > bestS || (s == bestS && ix < bestI)) { bestS = s; bestI = ix; }
            }
        } else {
            // overflow fallback (astronomically rare): exact full scan
            for (int ix = 0; ix < KCODES; ix++) {
                const float4* c4 = (const float4*)(cb + (size_t)ix * DIMS);
                float a0 = 0.f, a1 = 0.f, a2 = 0.f, a3 = 0.f;
#pragma unroll
                for (int q = 0; q < 16; q++) {
                    float4 cv = c4[q];
                    float4 xv = xr[q];
                    a0 = fmaf(xv.x, cv.x, a0);
                    a1 = fmaf(xv.y, cv.y, a1);
                    a2 = fmaf(xv.z, cv.z, a2);
                    a3 = fmaf(xv.w, cv.w, a3);
                }
                float s = (a0 + a1) + (a2 + a3) - CN[ix];
                if (s > bestS) { bestS = s; bestI = ix; }
            }
        }
        TK[r] = bestI;
        out[QOUT + row0 + r] = (float)bestI;
        atomicAdd(&g_counts[bestI], 1u);
    }
    __syncthreads();

    // ---- quantized + straight-through + losses (cooperative, coalesced) ----
    float esum = 0.0f, qsum = 0.0f;
#pragma unroll
    for (int i = 0; i < 4; i++) {
        int idx = tid + i * THREADS;
        int r = idx >> 4, q = idx & 15;
        int ix = TK[r];
        float4 cv = *(const float4*)(cb + (size_t)ix * DIMS + q * 4);
        float4 xv = *(const float4*)(inp + (size_t)(row0 + r) * DIMS + q * 4);
        float d0v = cv.x - xv.x, d1v = cv.y - xv.y, d2v = cv.z - xv.z, d3v = cv.w - xv.w;
        float q0 = xv.x + d0v, q1 = xv.y + d1v, q2 = xv.z + d2v, q3 = xv.w + d3v;
        float e0 = q0 - xv.x, e1 = q1 - xv.y, e2 = q2 - xv.z, e3 = q3 - xv.w;
        esum += e0 * e0 + e1 * e1 + e2 * e2 + e3 * e3;
        qsum += d0v * d0v + d1v * d1v + d2v * d2v + d3v * d3v;
        *(float4*)(out + (size_t)(row0 + r) * DIMS + q * 4) = make_float4(q0, q1, q2, q3);
    }
#pragma unroll
    for (int off = 16; off > 0; off >>= 1) {
        esum += __shfl_xor_sync(0xffffffffu, esum, off);
        qsum += __shfl_xor_sync(0xffffffffu, qsum, off);
    }
    if (lane == 0) {
        atomicAdd(&g_loss[0], esum);
        atomicAdd(&g_loss[1], qsum);
    }

    // ---- last-CTA finalize ----
    if (tid == 0) {
        __threadfence();
        *FLAG = (atomicAdd(&g_done, 1u) == GRID - 1) ? 1 : 0;
    }
    __syncthreads();
    if (*FLAG) {
        volatile unsigned* vc = g_counts;
        float part = 0.0f;
#pragma unroll
        for (int i = 0; i < 2; i++) {
            float p = (float)vc[tid + i * THREADS] / (float)N_ROWS;
            part += -p * logf(p + 1e-10f);
        }
#pragma unroll
        for (int off = 16; off > 0; off >>= 1)
            part += __shfl_xor_sync(0xffffffffu, part, off);
        float* red = (float*)RM;
        if (lane == 0) red[w] = part;
        __syncthreads();
        if (tid == 0) {
            float H = 0.0f;
#pragma unroll
            for (int i = 0; i < 16; i++) H += red[i];
            volatile float* vl = g_loss;
            float inv = 1.0f / (float)((long long)N_ROWS * DIMS);
            float e_mean = vl[0] * inv;
            float q_mean = vl[1] * inv;
            float commit = 0.25f * e_mean;
            out[QOUT + N_ROWS + 0] = commit + q_mean;
            out[QOUT + N_ROWS + 1] = commit;
            out[QOUT + N_ROWS + 2] = q_mean;
            out[QOUT + N_ROWS + 3] = expf(H);
        }
    }
}

extern "C" void kernel_launch(void* const* d_in, const int* in_sizes, int n_in,
                              void* d_out, int out_size)
{
    const float* inp = (const float*)d_in[0];
    const float* cb  = (const float*)d_in[1];
    float* out = (float*)d_out;

    cudaFuncSetAttribute(vq_main, cudaFuncAttributeMaxDynamicSharedMemorySize, SMEM_TOTAL);

    vq_prep<<<1, 1024>>>(cb);
    vq_main<<<GRID, THREADS, SMEM_TOTAL>>>(inp, cb, out);
}